// round 16
// baseline (speedup 1.0000x reference)
#include <cuda_runtime.h>
#include <cuda_fp16.h>
#include <math.h>
#include <stdint.h>

// ---------------- problem constants ----------------
#define FRAMES 4096      // B*T
#define HW     121
#define FCK    7744      // = 121*64, pixel-major: k = pix*64 + cin
#define XSTRIDE 72       // X row stride in fp16 elems -> 144B
#define XROWS   172      // 13x13=169 plane + overread pad
#define BFRAGS  9216     // uint2 fragments per layer
#define HALF0_FRAGS 5120 // taps 0-4
#define HALF1_FRAGS 4096 // taps 5-8
#define RING_BYTES  40960
#define FC_KS   484      // 7744/16
#define FC_SPLITS 4
#define FC_KS_PER 121    // 484/4
#define FC_TILE_CHUNKS 11
#define FC_TILE_HALVES 176
#define FC_AS_STRIDE 184     // smem row stride in halves (368B)
#define NBF (8 * BFRAGS)     // 73728 conv fragments
#define NWF (FC_KS * 256)    // 123904 fc fragments
#define NWIH 4096            // w_ih fragments

// conv smem offsets (bytes)
#define SM_X     0
#define SM_RING0 24768
#define SM_RING1 (SM_RING0 + RING_BYTES)
#define SM_BIAS  (SM_RING1 + RING_BYTES)
#define SM_TOTAL (SM_BIAS + 256)

// ---------------- global scratch ----------------
__device__ __half g_conv_out[(size_t)FRAMES * FCK];   // [frame][pix][oc]
__device__ float g_fc_part[(size_t)FC_SPLITS * FRAMES * 64];
__device__ float g_xg[(size_t)FRAMES * 256];
__device__ float g_lstm[(size_t)FRAMES * 64];
__device__ uint2 g_bf[NBF];
__device__ uint2 g_wfc[NWF];
__device__ uint2 g_wih[NWIH];
__device__ unsigned g_cnt[FRAMES / 32];   // per-mblock arrival counters

// ---------------- helpers ----------------
__device__ __forceinline__ uint32_t smem_u32(const void* p) {
    uint32_t a;
    asm("{ .reg .u64 t; cvta.to.shared.u64 t, %1; cvt.u32.u64 %0, t; }" : "=r"(a) : "l"(p));
    return a;
}
__device__ __forceinline__ unsigned pack_half2(__half a, __half b) {
    return (unsigned)__half_as_ushort(a) | ((unsigned)__half_as_ushort(b) << 16);
}
__device__ __forceinline__ void mma_f16(float* d, unsigned a0, unsigned a1,
                                        unsigned a2, unsigned a3,
                                        unsigned b0, unsigned b1) {
    asm volatile("mma.sync.aligned.m16n8k16.row.col.f32.f16.f16.f32 "
                 "{%0,%1,%2,%3},{%4,%5,%6,%7},{%8,%9},{%0,%1,%2,%3};\n"
                 : "+f"(d[0]), "+f"(d[1]), "+f"(d[2]), "+f"(d[3])
                 : "r"(a0), "r"(a1), "r"(a2), "r"(a3), "r"(b0), "r"(b1));
}
__device__ __forceinline__ void cp16(uint32_t dst, const void* src) {
    asm volatile("cp.async.cg.shared.global [%0], [%1], 16;" :: "r"(dst), "l"(src));
}
__device__ __forceinline__ void cp_commit() {
    asm volatile("cp.async.commit_group;" ::: "memory");
}
template <int N>
__device__ __forceinline__ void cp_wait() {
    asm volatile("cp.async.wait_group %0;" :: "n"(N) : "memory");
}
__device__ __forceinline__ float fast_sigmoid(float x) {
    return __fdividef(1.f, 1.f + __expf(-x));
}
__device__ __forceinline__ float fast_tanh(float x) {
    return 1.f - __fdividef(2.f, __expf(2.f * x) + 1.f);
}

// =====================================================================
// Kernel 0: merged weight prep (conv + FC + w_ih fragments) + counter reset
// =====================================================================
__global__ void prep_kernel(const float* __restrict__ c0w, const float* __restrict__ cws,
                            const float* __restrict__ fcw, const float* __restrict__ wih)
{
    if (blockIdx.x == 0 && threadIdx.x < FRAMES / 32) g_cnt[threadIdx.x] = 0u;

    int t = blockIdx.x * 256 + threadIdx.x;
    if (t < NBF) {
        int lane = t & 31;
        int n    = (t >> 5) & 7;
        int ks   = (t >> 8) & 3;
        int tap  = (t >> 10) % 9;
        int L    = t / BFRAGS;
        int oc   = n * 8 + (lane >> 2);
        int ic0  = ks * 16 + 2 * (lane & 3);
        __half h[4];
#pragma unroll
        for (int e = 0; e < 4; ++e) {
            int ic = ic0 + (e >> 1) * 8 + (e & 1);
            float v = 0.f;
            if (L == 0) { if (ks == 0 && ic < 9) v = c0w[oc * 81 + ic * 9 + tap]; }
            else        { v = cws[(size_t)(L - 1) * 36864 + oc * 576 + ic * 9 + tap]; }
            h[e] = __float2half(v);
        }
        g_bf[t] = make_uint2(pack_half2(h[0], h[1]), pack_half2(h[2], h[3]));
    } else if (t < NBF + NWF) {
        int t2 = t - NBF;
        int lane = t2 & 31;
        int n    = (t2 >> 5) & 7;
        int ks   = t2 >> 8;
        int oc   = n * 8 + (lane >> 2);
        int k0   = ks * 16 + 2 * (lane & 3);
        __half h[4];
#pragma unroll
        for (int e = 0; e < 4; ++e) {
            int k = k0 + (e >> 1) * 8 + (e & 1);   // pixel-major k
            int pix = k >> 6, cin = k & 63;
            h[e] = __float2half(fcw[(size_t)oc * FCK + cin * HW + pix]);
        }
        g_wfc[t2] = make_uint2(pack_half2(h[0], h[1]), pack_half2(h[2], h[3]));
    } else if (t < NBF + NWF + NWIH) {
        int t3 = t - NBF - NWF;
        int lane = t3 & 31;
        int n    = (t3 >> 5) & 31;
        int ks   = t3 >> 10;
        int oc   = n * 8 + (lane >> 2);
        int ic0  = ks * 16 + 2 * (lane & 3);
        __half h[4];
#pragma unroll
        for (int e = 0; e < 4; ++e) {
            int ic = ic0 + (e >> 1) * 8 + (e & 1);
            h[e] = __float2half(wih[oc * 64 + ic]);
        }
        g_wih[t3] = make_uint2(pack_half2(h[0], h[1]), pack_half2(h[2], h[3]));
    }
}

// =====================================================================
// Kernel 1: fused 8-layer conv stack (unchanged — at HMMA floor)
// =====================================================================
__global__ __launch_bounds__(256, 2)
void conv_mma_kernel(const float* __restrict__ x,
                     const float* __restrict__ c0b, const float* __restrict__ cbs)
{
    extern __shared__ char smraw[];
    __half* Xh = (__half*)(smraw + SM_X);
    uint2* ring[2] = { (uint2*)(smraw + SM_RING0), (uint2*)(smraw + SM_RING1) };
    float* bias = (float*)(smraw + SM_BIAS);
    const uint32_t ring_u32[2] = { smem_u32(smraw + SM_RING0), smem_u32(smraw + SM_RING1) };

    const int f    = blockIdx.x;
    const int tid  = threadIdx.x;
    const int warp = tid >> 5;
    const int lane = tid & 31;
    const int qid  = lane >> 2;
    const int tq   = lane & 3;

    const int m_lo = 16 * warp + qid;
    const int m_hi = m_lo + 8;
    const bool v_lo = (m_lo < HW);
    const bool v_hi = (m_hi < HW);
    const int ob_lo = v_lo ? (13 * (m_lo / 11) + (m_lo % 11)) : 143;
    const int ob_hi = v_hi ? (13 * (m_hi / 11) + (m_hi % 11)) : 143;

    {
        const uint4* src = (const uint4*)(g_bf);
        for (int i = tid; i < HALF0_FRAGS / 2; i += 256)
            cp16(ring_u32[0] + i * 16, src + i);
        cp_commit();
    }
    {
        unsigned* Xz = (unsigned*)Xh;
        for (int i = tid; i < XROWS * XSTRIDE / 2; i += 256) Xz[i] = 0u;
    }
    __syncthreads();

    const float* xf = x + (size_t)f * 9 * HW;
    for (int i = tid; i < 9 * HW; i += 256) {
        int ic = i / HW, pix = i % HW;
        int row = 13 * (pix / 11) + (pix % 11) + 14;
        Xh[row * XSTRIDE + ic] = __float2half(xf[i]);
    }
    __half* gout = g_conv_out + (size_t)f * FCK;

    float acc[8][4];

    for (int c = 0; c < 16; ++c) {
        const int L = c >> 1, half = c & 1, buf = c & 1;

        if (c + 1 < 16) {
            const int Ln = (c + 1) >> 1, hn = (c + 1) & 1;
            const uint4* src = (const uint4*)(g_bf + (size_t)Ln * BFRAGS
                                              + (hn ? HALF0_FRAGS : 0));
            const int n16 = (hn ? HALF1_FRAGS : HALF0_FRAGS) / 2;
            const uint32_t dst = ring_u32[1 - buf];
            for (int i = tid; i < n16; i += 256) cp16(dst + i * 16, src + i);
            cp_commit();
            cp_wait<1>();
        } else {
            cp_wait<0>();
        }
        if (half == 0 && tid < 64)
            bias[tid] = (L == 0) ? c0b[tid] : cbs[(L - 1) * 64 + tid];
        __syncthreads();

        if (half == 0) {
#pragma unroll
            for (int n = 0; n < 8; ++n) {
                float b0 = bias[n * 8 + 2 * tq], b1 = bias[n * 8 + 2 * tq + 1];
                acc[n][0] = b0; acc[n][1] = b1; acc[n][2] = b0; acc[n][3] = b1;
            }
        }

        const int KS = (L == 0) ? 1 : 4;
        const int tap0 = half ? 5 : 0;
        const int ntap = half ? 4 : 5;
        const uint2* rb = ring[buf];

        for (int t = 0; t < ntap; ++t) {
            const int tap = tap0 + t;
            const int off = 13 * (tap / 3) + (tap % 3);
            const __half* plo_base = Xh + (ob_lo + off) * XSTRIDE;
            const __half* phi_base = Xh + (ob_hi + off) * XSTRIDE;
            for (int ks = 0; ks < KS; ++ks) {
                const int cb = ks * 16 + 2 * tq;
                unsigned a0 = *(const unsigned*)(plo_base + cb);
                unsigned a1 = *(const unsigned*)(phi_base + cb);
                unsigned a2 = *(const unsigned*)(plo_base + cb + 8);
                unsigned a3 = *(const unsigned*)(phi_base + cb + 8);

                const uint2* bp = rb + ((t * 4 + ks) * 8) * 32 + lane;
#pragma unroll
                for (int n = 0; n < 8; ++n) {
                    uint2 b = bp[n * 32];
                    mma_f16(acc[n], a0, a1, a2, a3, b.x, b.y);
                }
            }
        }

        if (half == 1) {
            __syncthreads();
#pragma unroll
            for (int n = 0; n < 8; ++n) {
                const int oc0 = n * 8 + 2 * tq;
                if (v_lo) {
                    __half h0 = __float2half(fmaxf(acc[n][0], 0.f));
                    __half h1 = __float2half(fmaxf(acc[n][1], 0.f));
                    if (L < 7)
                        *(unsigned*)(Xh + (ob_lo + 14) * XSTRIDE + oc0) = pack_half2(h0, h1);
                    else
                        *(unsigned*)(gout + (size_t)m_lo * 64 + oc0) = pack_half2(h0, h1);
                }
                if (v_hi) {
                    __half h0 = __float2half(fmaxf(acc[n][2], 0.f));
                    __half h1 = __float2half(fmaxf(acc[n][3], 0.f));
                    if (L < 7)
                        *(unsigned*)(Xh + (ob_hi + 14) * XSTRIDE + oc0) = pack_half2(h0, h1);
                    else
                        *(unsigned*)(gout + (size_t)m_hi * 64 + oc0) = pack_half2(h0, h1);
                }
            }
        }
        __syncthreads();
    }
}

// =====================================================================
// Kernel 2: FC GEMM + fused xgates tail.
// Split-K x4 grid (128,4); after storing partials, the 4th-arriving CTA
// of each m-block runs the xgates body (reduce+relu -> fp16 -> mma).
// =====================================================================
__global__ __launch_bounds__(256)
void fc_mma_kernel(const float* __restrict__ fc_b,
                   const float* __restrict__ b_ih, const float* __restrict__ b_hh)
{
    __shared__ __half As[3][32][FC_AS_STRIDE];
    __shared__ unsigned s_old;

    const int m0 = blockIdx.x * 32;
    const int split = blockIdx.y;
    const int ks0 = split * FC_KS_PER;
    const int tid = threadIdx.x;
    const int warp = tid >> 5, lane = tid & 31;
    const int mt = warp >> 2, nq = warp & 3;
    const int qid = lane >> 2, tq = lane & 3;

    const int bo0 = (nq * 2) * 32 + lane;
    const int bo1 = bo0 + 32;

    const int lm_row = mt * 16 + (lane & 15);
    const int lm_col = (lane >> 4) * 8;

    float acc[2][4] = {};
    const size_t kbase0 = (size_t)ks0 * 16;

#pragma unroll
    for (int p = 0; p < 2; ++p) {
        const size_t kb = kbase0 + (size_t)p * FC_TILE_HALVES;
        for (int i = tid; i < 704; i += 256) {
            int r = i / 22, seg = i % 22;
            cp16(smem_u32(&As[p][r][seg * 8]),
                 &g_conv_out[(size_t)(m0 + r) * FCK + kb + seg * 8]);
        }
        cp_commit();
    }

    for (int t = 0; t < FC_TILE_CHUNKS; ++t) {
        const int buf = t % 3;
        if (t + 1 < FC_TILE_CHUNKS) cp_wait<1>(); else cp_wait<0>();
        __syncthreads();

        if (t + 2 < FC_TILE_CHUNKS) {
            const size_t kb = kbase0 + (size_t)(t + 2) * FC_TILE_HALVES;
            const int pb = (t + 2) % 3;
            for (int i = tid; i < 704; i += 256) {
                int r = i / 22, seg = i % 22;
                cp16(smem_u32(&As[pb][r][seg * 8]),
                     &g_conv_out[(size_t)(m0 + r) * FCK + kb + seg * 8]);
            }
            cp_commit();
        }

        const uint32_t lmbase = smem_u32(&As[buf][lm_row][lm_col]);
#pragma unroll
        for (int c = 0; c < 11; ++c) {
            unsigned a0, a1, a2, a3;
            asm volatile("ldmatrix.sync.aligned.m8n8.x4.shared.b16 {%0,%1,%2,%3}, [%4];"
                         : "=r"(a0), "=r"(a1), "=r"(a2), "=r"(a3)
                         : "r"(lmbase + c * 32));
            const int ks = ks0 + t * 11 + c;
            uint2 b0 = g_wfc[(size_t)ks * 256 + bo0];
            uint2 b1 = g_wfc[(size_t)ks * 256 + bo1];
            mma_f16(acc[0], a0, a1, a2, a3, b0.x, b0.y);
            mma_f16(acc[1], a0, a1, a2, a3, b1.x, b1.y);
        }
    }

    // store partials
    float* dst = g_fc_part + (size_t)split * FRAMES * 64;
#pragma unroll
    for (int j = 0; j < 2; ++j) {
        const int col = (nq * 2 + j) * 8 + 2 * tq;
#pragma unroll
        for (int hf = 0; hf < 2; ++hf) {
            int m = m0 + mt * 16 + qid + 8 * hf;
            dst[(size_t)m * 64 + col]     = acc[j][2 * hf];
            dst[(size_t)m * 64 + col + 1] = acc[j][2 * hf + 1];
        }
    }

    // ---- arrival protocol: 4th CTA of this m-block runs xgates ----
    __threadfence();
    __syncthreads();
    if (tid == 0) s_old = atomicAdd(&g_cnt[blockIdx.x], 1u);
    __syncthreads();
    if (s_old != FC_SPLITS - 1) return;
    __threadfence();   // acquire: other splits' partials now visible

    // ---- xgates body (frames m0..m0+31) ----
    __half* Ax = &As[0][0][0];   // reuse, stride FC_AS_STRIDE halves
    {
        const int fr = tid >> 3, cin = (tid & 7) * 8;
        const size_t idx = (size_t)(m0 + fr) * 64 + cin;
        unsigned packed[4];
#pragma unroll
        for (int p = 0; p < 4; ++p) {
            __half h2[2];
#pragma unroll
            for (int e = 0; e < 2; ++e) {
                const size_t id = idx + p * 2 + e;
                float v = g_fc_part[id]
                        + g_fc_part[(size_t)FRAMES * 64 + id]
                        + g_fc_part[(size_t)2 * FRAMES * 64 + id]
                        + g_fc_part[(size_t)3 * FRAMES * 64 + id]
                        + fc_b[cin + p * 2 + e];
                h2[e] = __float2half(fmaxf(v, 0.f));
            }
            packed[p] = pack_half2(h2[0], h2[1]);
        }
#pragma unroll
        for (int p = 0; p < 4; ++p)
            *(unsigned*)&Ax[fr * FC_AS_STRIDE + cin + p * 2] = packed[p];
    }
    __syncthreads();

    float xacc[8][4] = {};
#pragma unroll
    for (int ks = 0; ks < 4; ++ks) {
        unsigned a0, a1, a2, a3;
        asm volatile("ldmatrix.sync.aligned.m8n8.x4.shared.b16 {%0,%1,%2,%3}, [%4];"
                     : "=r"(a0), "=r"(a1), "=r"(a2), "=r"(a3)
                     : "r"(smem_u32(&Ax[lm_row * FC_AS_STRIDE + lm_col + ks * 16])));
#pragma unroll
        for (int j = 0; j < 8; ++j) {
            uint2 b = g_wih[(ks * 32 + nq * 8 + j) * 32 + lane];
            mma_f16(xacc[j], a0, a1, a2, a3, b.x, b.y);
        }
    }

#pragma unroll
    for (int j = 0; j < 8; ++j) {
        const int col = (nq * 8 + j) * 8 + 2 * tq;
        const float sb0 = b_ih[col] + b_hh[col];
        const float sb1 = b_ih[col + 1] + b_hh[col + 1];
#pragma unroll
        for (int hf = 0; hf < 2; ++hf) {
            const int m = m0 + mt * 16 + qid + 8 * hf;
            g_xg[(size_t)m * 256 + col]     = xacc[j][2 * hf] + sb0;
            g_xg[(size_t)m * 256 + col + 1] = xacc[j][2 * hf + 1] + sb1;
        }
    }
}

// =====================================================================
// Kernel 4: recurrent LSTM — packed f32x2 FMA (unchanged)
// =====================================================================
__global__ __launch_bounds__(512)
void lstm_kernel(const float* __restrict__ w_hh)
{
    __shared__ float h_s[2][64];
    const int b = blockIdx.x;
    const int tid = threadIdx.x;
    const int u   = tid >> 3;
    const int gq  = (tid >> 1) & 3;
    const int hh  = tid & 1;
    const int lane = tid & 31;
    const int base = lane & 24;

    const int grow = gq * 64 + u;
    unsigned long long w2[16];
#pragma unroll
    for (int k = 0; k < 16; ++k) {
        float lo = w_hh[grow * 64 + hh * 32 + 2 * k];
        float hi = w_hh[grow * 64 + hh * 32 + 2 * k + 1];
        asm("mov.b64 %0, {%1, %2};" : "=l"(w2[k]) : "f"(lo), "f"(hi));
    }
    float c = 0.f;
    if (tid < 64) h_s[0][tid] = 0.f;
    __syncthreads();

    const float* xgb = g_xg + (size_t)b * 128 * 256;
    float* lob = g_lstm + (size_t)b * 128 * 64;

    float xnext = (hh == 0) ? xgb[grow] : 0.f;
    for (int t = 0; t < 128; ++t) {
        const unsigned long long* hp =
            (const unsigned long long*)(h_s[t & 1] + hh * 32);
        unsigned long long a0 = 0ull, a1 = 0ull;
#pragma unroll
        for (int k = 0; k < 8; ++k) {
            asm("fma.rn.f32x2 %0, %1, %2, %0;" : "+l"(a0) : "l"(w2[2 * k]), "l"(hp[2 * k]));
            asm("fma.rn.f32x2 %0, %1, %2, %0;" : "+l"(a1) : "l"(w2[2 * k + 1]), "l"(hp[2 * k + 1]));
        }
        unsigned long long at;
        asm("add.rn.f32x2 %0, %1, %2;" : "=l"(at) : "l"(a0), "l"(a1));
        float slo, shi;
        asm("mov.b64 {%0, %1}, %2;" : "=f"(slo), "=f"(shi) : "l"(at));
        float s = slo + shi;
        s += __shfl_xor_sync(0xffffffffu, s, 1);
        s += xnext;
        if (hh == 0 && t < 127) xnext = xgb[(t + 1) * 256 + grow];

        float act = (gq == 2) ? fast_tanh(s) : fast_sigmoid(s);
        float ai = __shfl_sync(0xffffffffu, act, base + 0);
        float af = __shfl_sync(0xffffffffu, act, base + 2);
        float ag = __shfl_sync(0xffffffffu, act, base + 4);
        float ao = __shfl_sync(0xffffffffu, act, base + 6);
        if ((lane & 7) == 0) {
            c = af * c + ai * ag;
            float h = ao * fast_tanh(c);
            lob[t * 64 + u] = h;
            h_s[(t + 1) & 1][u] = h;
        }
        __syncthreads();
    }
}

// =====================================================================
// Kernel 5: fused policy/value heads — batched two-phase (unchanged)
// =====================================================================
__global__ __launch_bounds__(256)
void heads_kernel(const float* __restrict__ p1w, const float* __restrict__ p1b,
                  const float* __restrict__ p2w, const float* __restrict__ p2b,
                  const float* __restrict__ v1w, const float* __restrict__ v1b,
                  const float* __restrict__ v2w, const float* __restrict__ v2b,
                  float* __restrict__ out)
{
    __shared__ float h_s[32][64];
    __shared__ float u_s[32][260];
    __shared__ float p2s[6 * 128];
    __shared__ float v2s[128];

    const int f0 = blockIdx.x * 32;
    const int t = threadIdx.x;

    const float* wsrc = (t < 128) ? (p1w + t * 64) : (v1w + (t - 128) * 64);
    float w[64];
#pragma unroll
    for (int k = 0; k < 64; ++k) w[k] = wsrc[k];
    const float bias = (t < 128) ? p1b[t] : v1b[t - 128];

    for (int i = t; i < 32 * 64; i += 256) h_s[i / 64][i % 64] = g_lstm[(size_t)f0 * 64 + i];
    for (int i = t; i < 768; i += 256) p2s[i] = p2w[i];
    if (t < 128) v2s[t] = v2w[t];
    __syncthreads();

    for (int fi = 0; fi < 32; fi += 2) {
        float sA = bias, sB = bias;
#pragma unroll
        for (int k = 0; k < 64; ++k) {
            sA = fmaf(w[k], h_s[fi][k], sA);
            sB = fmaf(w[k], h_s[fi + 1][k], sB);
        }
        u_s[fi][t]     = fmaxf(sA, 0.f);
        u_s[fi + 1][t] = fmaxf(sB, 0.f);
    }
    __syncthreads();

    const int f = t >> 3, j = t & 7;
    if (j < 6) {
        const float* pw = p2s + j * 128;
        const float* us = u_s[f];
        float s0 = 0.f, s1 = 0.f;
#pragma unroll
        for (int k = 0; k < 128; k += 2) {
            s0 = fmaf(pw[k], us[k], s0);
            s1 = fmaf(pw[k + 1], us[k + 1], s1);
        }
        out[(f0 + f) * 6 + j] = s0 + s1 + p2b[j];
    } else if (j == 6) {
        const float* us = u_s[f] + 128;
        float s0 = 0.f, s1 = 0.f;
#pragma unroll
        for (int k = 0; k < 128; k += 2) {
            s0 = fmaf(v2s[k], us[k], s0);
            s1 = fmaf(v2s[k + 1], us[k + 1], s1);
        }
        out[FRAMES * 6 + f0 + f] = s0 + s1 + v2b[0];
    }
}

// =====================================================================
extern "C" void kernel_launch(void* const* d_in, const int* in_sizes, int n_in,
                              void* d_out, int out_size)
{
    const float* x    = (const float*)d_in[0];
    const float* c0w  = (const float*)d_in[1];
    const float* c0b  = (const float*)d_in[2];
    const float* cws  = (const float*)d_in[3];
    const float* cbs  = (const float*)d_in[4];
    const float* fcw  = (const float*)d_in[5];
    const float* fcb  = (const float*)d_in[6];
    const float* wih  = (const float*)d_in[7];
    const float* whh  = (const float*)d_in[8];
    const float* bih  = (const float*)d_in[9];
    const float* bhh  = (const float*)d_in[10];
    const float* p1w  = (const float*)d_in[11];
    const float* p1b  = (const float*)d_in[12];
    const float* p2w  = (const float*)d_in[13];
    const float* p2b  = (const float*)d_in[14];
    const float* v1w  = (const float*)d_in[15];
    const float* v1b  = (const float*)d_in[16];
    const float* v2w  = (const float*)d_in[17];
    const float* v2b  = (const float*)d_in[18];
    float* out = (float*)d_out;

    cudaFuncSetAttribute(conv_mma_kernel,
                         cudaFuncAttributeMaxDynamicSharedMemorySize, SM_TOTAL);

    prep_kernel<<<(NBF + NWF + NWIH + 255) / 256, 256>>>(c0w, cws, fcw, wih);
    conv_mma_kernel<<<FRAMES, 256, SM_TOTAL>>>(x, c0b, cbs);
    fc_mma_kernel<<<dim3(FRAMES / 32, FC_SPLITS), 256>>>(fcb, bih, bhh);
    lstm_kernel<<<32, 512>>>(whh);
    heads_kernel<<<FRAMES / 32, 256>>>(p1w, p1b, p2w, p2b, v1w, v1b, v2w, v2b, out);
}

// round 17
// speedup vs baseline: 1.0215x; 1.0215x over previous
#include <cuda_runtime.h>
#include <cuda_fp16.h>
#include <math.h>
#include <stdint.h>

// ---------------- problem constants ----------------
#define FRAMES 4096      // B*T
#define HW     121
#define FCK    7744      // = 121*64, pixel-major: k = pix*64 + cin
#define XSTRIDE 72       // X row stride in fp16 elems -> 144B
#define XROWS   172      // 13x13=169 plane + overread pad
#define BFRAGS  9216     // uint2 fragments per layer
#define HALF0_FRAGS 5120 // taps 0-4
#define HALF1_FRAGS 4096 // taps 5-8
#define RING_BYTES  40960
#define FC_KS   484      // 7744/16
#define FC_SPLITS 4
#define FC_KS_PER 121    // 484/4
#define FC_TILE_CHUNKS 11
#define FC_TILE_HALVES 176
#define FC_AS_STRIDE 184     // smem row stride in halves (368B)
#define NBF (8 * BFRAGS)     // 73728 conv fragments
#define NWF (FC_KS * 256)    // 123904 fc fragments
#define NWIH 4096            // w_ih fragments

// conv smem offsets (bytes)
#define SM_X     0
#define SM_RING0 24768
#define SM_RING1 (SM_RING0 + RING_BYTES)
#define SM_BIAS  (SM_RING1 + RING_BYTES)
#define SM_TOTAL (SM_BIAS + 256)

// ---------------- global scratch ----------------
__device__ __half g_conv_out[(size_t)FRAMES * FCK];   // [frame][pix][oc]
__device__ float g_fc_part[(size_t)FC_SPLITS * FRAMES * 64];
__device__ float g_xg[(size_t)FRAMES * 256];
__device__ float g_lstm[(size_t)FRAMES * 64];
__device__ uint2 g_bf[NBF];
__device__ uint2 g_wfc[NWF];
__device__ uint2 g_wih[NWIH];

// ---------------- helpers ----------------
__device__ __forceinline__ uint32_t smem_u32(const void* p) {
    uint32_t a;
    asm("{ .reg .u64 t; cvta.to.shared.u64 t, %1; cvt.u32.u64 %0, t; }" : "=r"(a) : "l"(p));
    return a;
}
__device__ __forceinline__ unsigned pack_half2(__half a, __half b) {
    return (unsigned)__half_as_ushort(a) | ((unsigned)__half_as_ushort(b) << 16);
}
__device__ __forceinline__ void mma_f16(float* d, unsigned a0, unsigned a1,
                                        unsigned a2, unsigned a3,
                                        unsigned b0, unsigned b1) {
    asm volatile("mma.sync.aligned.m16n8k16.row.col.f32.f16.f16.f32 "
                 "{%0,%1,%2,%3},{%4,%5,%6,%7},{%8,%9},{%0,%1,%2,%3};\n"
                 : "+f"(d[0]), "+f"(d[1]), "+f"(d[2]), "+f"(d[3])
                 : "r"(a0), "r"(a1), "r"(a2), "r"(a3), "r"(b0), "r"(b1));
}
__device__ __forceinline__ void cp16(uint32_t dst, const void* src) {
    asm volatile("cp.async.cg.shared.global [%0], [%1], 16;" :: "r"(dst), "l"(src));
}
__device__ __forceinline__ void cp_commit() {
    asm volatile("cp.async.commit_group;" ::: "memory");
}
template <int N>
__device__ __forceinline__ void cp_wait() {
    asm volatile("cp.async.wait_group %0;" :: "n"(N) : "memory");
}
__device__ __forceinline__ float fast_sigmoid(float x) {
    return __fdividef(1.f, 1.f + __expf(-x));
}
__device__ __forceinline__ float fast_tanh(float x) {
    return 1.f - __fdividef(2.f, __expf(2.f * x) + 1.f);
}

// =====================================================================
// Kernel 0: merged weight prep (conv + FC + w_ih fragments)
// =====================================================================
__global__ void prep_kernel(const float* __restrict__ c0w, const float* __restrict__ cws,
                            const float* __restrict__ fcw, const float* __restrict__ wih)
{
    int t = blockIdx.x * 256 + threadIdx.x;
    if (t < NBF) {
        int lane = t & 31;
        int n    = (t >> 5) & 7;
        int ks   = (t >> 8) & 3;
        int tap  = (t >> 10) % 9;
        int L    = t / BFRAGS;
        int oc   = n * 8 + (lane >> 2);
        int ic0  = ks * 16 + 2 * (lane & 3);
        __half h[4];
#pragma unroll
        for (int e = 0; e < 4; ++e) {
            int ic = ic0 + (e >> 1) * 8 + (e & 1);
            float v = 0.f;
            if (L == 0) { if (ks == 0 && ic < 9) v = c0w[oc * 81 + ic * 9 + tap]; }
            else        { v = cws[(size_t)(L - 1) * 36864 + oc * 576 + ic * 9 + tap]; }
            h[e] = __float2half(v);
        }
        g_bf[t] = make_uint2(pack_half2(h[0], h[1]), pack_half2(h[2], h[3]));
    } else if (t < NBF + NWF) {
        int t2 = t - NBF;
        int lane = t2 & 31;
        int n    = (t2 >> 5) & 7;
        int ks   = t2 >> 8;
        int oc   = n * 8 + (lane >> 2);
        int k0   = ks * 16 + 2 * (lane & 3);
        __half h[4];
#pragma unroll
        for (int e = 0; e < 4; ++e) {
            int k = k0 + (e >> 1) * 8 + (e & 1);   // pixel-major k
            int pix = k >> 6, cin = k & 63;
            h[e] = __float2half(fcw[(size_t)oc * FCK + cin * HW + pix]);
        }
        g_wfc[t2] = make_uint2(pack_half2(h[0], h[1]), pack_half2(h[2], h[3]));
    } else if (t < NBF + NWF + NWIH) {
        int t3 = t - NBF - NWF;
        int lane = t3 & 31;
        int n    = (t3 >> 5) & 31;
        int ks   = t3 >> 10;
        int oc   = n * 8 + (lane >> 2);
        int ic0  = ks * 16 + 2 * (lane & 3);
        __half h[4];
#pragma unroll
        for (int e = 0; e < 4; ++e) {
            int ic = ic0 + (e >> 1) * 8 + (e & 1);
            h[e] = __float2half(wih[oc * 64 + ic]);
        }
        g_wih[t3] = make_uint2(pack_half2(h[0], h[1]), pack_half2(h[2], h[3]));
    }
}

// =====================================================================
// Kernel 1: fused 8-layer conv stack (unchanged — at HMMA floor)
// =====================================================================
__global__ __launch_bounds__(256, 2)
void conv_mma_kernel(const float* __restrict__ x,
                     const float* __restrict__ c0b, const float* __restrict__ cbs)
{
    extern __shared__ char smraw[];
    __half* Xh = (__half*)(smraw + SM_X);
    uint2* ring[2] = { (uint2*)(smraw + SM_RING0), (uint2*)(smraw + SM_RING1) };
    float* bias = (float*)(smraw + SM_BIAS);
    const uint32_t ring_u32[2] = { smem_u32(smraw + SM_RING0), smem_u32(smraw + SM_RING1) };

    const int f    = blockIdx.x;
    const int tid  = threadIdx.x;
    const int warp = tid >> 5;
    const int lane = tid & 31;
    const int qid  = lane >> 2;
    const int tq   = lane & 3;

    const int m_lo = 16 * warp + qid;
    const int m_hi = m_lo + 8;
    const bool v_lo = (m_lo < HW);
    const bool v_hi = (m_hi < HW);
    const int ob_lo = v_lo ? (13 * (m_lo / 11) + (m_lo % 11)) : 143;
    const int ob_hi = v_hi ? (13 * (m_hi / 11) + (m_hi % 11)) : 143;

    {
        const uint4* src = (const uint4*)(g_bf);
        for (int i = tid; i < HALF0_FRAGS / 2; i += 256)
            cp16(ring_u32[0] + i * 16, src + i);
        cp_commit();
    }
    {
        unsigned* Xz = (unsigned*)Xh;
        for (int i = tid; i < XROWS * XSTRIDE / 2; i += 256) Xz[i] = 0u;
    }
    __syncthreads();

    const float* xf = x + (size_t)f * 9 * HW;
    for (int i = tid; i < 9 * HW; i += 256) {
        int ic = i / HW, pix = i % HW;
        int row = 13 * (pix / 11) + (pix % 11) + 14;
        Xh[row * XSTRIDE + ic] = __float2half(xf[i]);
    }
    __half* gout = g_conv_out + (size_t)f * FCK;

    float acc[8][4];

    for (int c = 0; c < 16; ++c) {
        const int L = c >> 1, half = c & 1, buf = c & 1;

        if (c + 1 < 16) {
            const int Ln = (c + 1) >> 1, hn = (c + 1) & 1;
            const uint4* src = (const uint4*)(g_bf + (size_t)Ln * BFRAGS
                                              + (hn ? HALF0_FRAGS : 0));
            const int n16 = (hn ? HALF1_FRAGS : HALF0_FRAGS) / 2;
            const uint32_t dst = ring_u32[1 - buf];
            for (int i = tid; i < n16; i += 256) cp16(dst + i * 16, src + i);
            cp_commit();
            cp_wait<1>();
        } else {
            cp_wait<0>();
        }
        if (half == 0 && tid < 64)
            bias[tid] = (L == 0) ? c0b[tid] : cbs[(L - 1) * 64 + tid];
        __syncthreads();

        if (half == 0) {
#pragma unroll
            for (int n = 0; n < 8; ++n) {
                float b0 = bias[n * 8 + 2 * tq], b1 = bias[n * 8 + 2 * tq + 1];
                acc[n][0] = b0; acc[n][1] = b1; acc[n][2] = b0; acc[n][3] = b1;
            }
        }

        const int KS = (L == 0) ? 1 : 4;
        const int tap0 = half ? 5 : 0;
        const int ntap = half ? 4 : 5;
        const uint2* rb = ring[buf];

        for (int t = 0; t < ntap; ++t) {
            const int tap = tap0 + t;
            const int off = 13 * (tap / 3) + (tap % 3);
            const __half* plo_base = Xh + (ob_lo + off) * XSTRIDE;
            const __half* phi_base = Xh + (ob_hi + off) * XSTRIDE;
            for (int ks = 0; ks < KS; ++ks) {
                const int cb = ks * 16 + 2 * tq;
                unsigned a0 = *(const unsigned*)(plo_base + cb);
                unsigned a1 = *(const unsigned*)(phi_base + cb);
                unsigned a2 = *(const unsigned*)(plo_base + cb + 8);
                unsigned a3 = *(const unsigned*)(phi_base + cb + 8);

                const uint2* bp = rb + ((t * 4 + ks) * 8) * 32 + lane;
#pragma unroll
                for (int n = 0; n < 8; ++n) {
                    uint2 b = bp[n * 32];
                    mma_f16(acc[n], a0, a1, a2, a3, b.x, b.y);
                }
            }
        }

        if (half == 1) {
            __syncthreads();
#pragma unroll
            for (int n = 0; n < 8; ++n) {
                const int oc0 = n * 8 + 2 * tq;
                if (v_lo) {
                    __half h0 = __float2half(fmaxf(acc[n][0], 0.f));
                    __half h1 = __float2half(fmaxf(acc[n][1], 0.f));
                    if (L < 7)
                        *(unsigned*)(Xh + (ob_lo + 14) * XSTRIDE + oc0) = pack_half2(h0, h1);
                    else
                        *(unsigned*)(gout + (size_t)m_lo * 64 + oc0) = pack_half2(h0, h1);
                }
                if (v_hi) {
                    __half h0 = __float2half(fmaxf(acc[n][2], 0.f));
                    __half h1 = __float2half(fmaxf(acc[n][3], 0.f));
                    if (L < 7)
                        *(unsigned*)(Xh + (ob_hi + 14) * XSTRIDE + oc0) = pack_half2(h0, h1);
                    else
                        *(unsigned*)(gout + (size_t)m_hi * 64 + oc0) = pack_half2(h0, h1);
                }
            }
        }
        __syncthreads();
    }
}

// =====================================================================
// Kernel 2: FC GEMM, cp.async + ldmatrix, triple-buffered, one sync/tile
// (round-15 version — fusion reverted)
// =====================================================================
__global__ __launch_bounds__(256)
void fc_mma_kernel()
{
    __shared__ __half As[3][32][FC_AS_STRIDE];

    const int m0 = blockIdx.x * 32;
    const int split = blockIdx.y;
    const int ks0 = split * FC_KS_PER;
    const int tid = threadIdx.x;
    const int warp = tid >> 5, lane = tid & 31;
    const int mt = warp >> 2, nq = warp & 3;
    const int qid = lane >> 2, tq = lane & 3;

    const int bo0 = (nq * 2) * 32 + lane;
    const int bo1 = bo0 + 32;

    const int lm_row = mt * 16 + (lane & 15);
    const int lm_col = (lane >> 4) * 8;

    float acc[2][4] = {};
    const size_t kbase0 = (size_t)ks0 * 16;

#pragma unroll
    for (int p = 0; p < 2; ++p) {
        const size_t kb = kbase0 + (size_t)p * FC_TILE_HALVES;
        for (int i = tid; i < 704; i += 256) {
            int r = i / 22, seg = i % 22;
            cp16(smem_u32(&As[p][r][seg * 8]),
                 &g_conv_out[(size_t)(m0 + r) * FCK + kb + seg * 8]);
        }
        cp_commit();
    }

    for (int t = 0; t < FC_TILE_CHUNKS; ++t) {
        const int buf = t % 3;
        if (t + 1 < FC_TILE_CHUNKS) cp_wait<1>(); else cp_wait<0>();
        __syncthreads();

        if (t + 2 < FC_TILE_CHUNKS) {
            const size_t kb = kbase0 + (size_t)(t + 2) * FC_TILE_HALVES;
            const int pb = (t + 2) % 3;
            for (int i = tid; i < 704; i += 256) {
                int r = i / 22, seg = i % 22;
                cp16(smem_u32(&As[pb][r][seg * 8]),
                     &g_conv_out[(size_t)(m0 + r) * FCK + kb + seg * 8]);
            }
            cp_commit();
        }

        const uint32_t lmbase = smem_u32(&As[buf][lm_row][lm_col]);
#pragma unroll
        for (int c = 0; c < 11; ++c) {
            unsigned a0, a1, a2, a3;
            asm volatile("ldmatrix.sync.aligned.m8n8.x4.shared.b16 {%0,%1,%2,%3}, [%4];"
                         : "=r"(a0), "=r"(a1), "=r"(a2), "=r"(a3)
                         : "r"(lmbase + c * 32));
            const int ks = ks0 + t * 11 + c;
            uint2 b0 = g_wfc[(size_t)ks * 256 + bo0];
            uint2 b1 = g_wfc[(size_t)ks * 256 + bo1];
            mma_f16(acc[0], a0, a1, a2, a3, b0.x, b0.y);
            mma_f16(acc[1], a0, a1, a2, a3, b1.x, b1.y);
        }
    }

    float* dst = g_fc_part + (size_t)split * FRAMES * 64;
#pragma unroll
    for (int j = 0; j < 2; ++j) {
        const int col = (nq * 2 + j) * 8 + 2 * tq;
#pragma unroll
        for (int hf = 0; hf < 2; ++hf) {
            int m = m0 + mt * 16 + qid + 8 * hf;
            dst[(size_t)m * 64 + col]     = acc[j][2 * hf];
            dst[(size_t)m * 64 + col + 1] = acc[j][2 * hf + 1];
        }
    }
}

// =====================================================================
// Kernel 3: fused xgates (reduce + relu -> fp16 -> mma) — round-15 version
// =====================================================================
__global__ __launch_bounds__(256)
void xgates_kernel(const float* __restrict__ fc_b,
                   const float* __restrict__ b_ih, const float* __restrict__ b_hh)
{
    __shared__ __half As[32][72];

    const int f0 = blockIdx.x * 32;
    const int tid = threadIdx.x;

    {
        const int e0 = tid * 8;
        const int fr = e0 >> 6, cin = e0 & 63;
        const size_t idx = (size_t)(f0 + fr) * 64 + cin;
        unsigned packed[4];
#pragma unroll
        for (int p = 0; p < 4; ++p) {
            __half h2[2];
#pragma unroll
            for (int e = 0; e < 2; ++e) {
                const size_t id = idx + p * 2 + e;
                float v = g_fc_part[id]
                        + g_fc_part[(size_t)FRAMES * 64 + id]
                        + g_fc_part[(size_t)2 * FRAMES * 64 + id]
                        + g_fc_part[(size_t)3 * FRAMES * 64 + id]
                        + fc_b[cin + p * 2 + e];
                h2[e] = __float2half(fmaxf(v, 0.f));
            }
            packed[p] = pack_half2(h2[0], h2[1]);
        }
#pragma unroll
        for (int p = 0; p < 4; ++p)
            *(unsigned*)&As[fr][cin + p * 2] = packed[p];
    }
    __syncthreads();

    const int warp = tid >> 5, lane = tid & 31;
    const int mt = warp >> 2, nq = warp & 3;
    const int qid = lane >> 2, tq = lane & 3;
    const int lm_row = mt * 16 + (lane & 15);
    const int lm_col = (lane >> 4) * 8;

    float acc[8][4] = {};

#pragma unroll
    for (int ks = 0; ks < 4; ++ks) {
        unsigned a0, a1, a2, a3;
        asm volatile("ldmatrix.sync.aligned.m8n8.x4.shared.b16 {%0,%1,%2,%3}, [%4];"
                     : "=r"(a0), "=r"(a1), "=r"(a2), "=r"(a3)
                     : "r"(smem_u32(&As[lm_row][lm_col + ks * 16])));
#pragma unroll
        for (int j = 0; j < 8; ++j) {
            uint2 b = g_wih[(ks * 32 + nq * 8 + j) * 32 + lane];
            mma_f16(acc[j], a0, a1, a2, a3, b.x, b.y);
        }
    }

#pragma unroll
    for (int j = 0; j < 8; ++j) {
        const int col = (nq * 8 + j) * 8 + 2 * tq;
        const float sb0 = b_ih[col] + b_hh[col];
        const float sb1 = b_ih[col + 1] + b_hh[col + 1];
#pragma unroll
        for (int hf = 0; hf < 2; ++hf) {
            const int m = f0 + mt * 16 + qid + 8 * hf;
            g_xg[(size_t)m * 256 + col]     = acc[j][2 * hf] + sb0;
            g_xg[(size_t)m * 256 + col + 1] = acc[j][2 * hf + 1] + sb1;
        }
    }
}

// =====================================================================
// Kernel 4: recurrent LSTM v3 — 256 threads / 8 warps, no hh split.
// lane = 4*u_local + gate: all 4 gates of a unit in adjacent lanes.
// 64-dot per thread via 32 f32x2 FMA on 4 independent accumulators;
// no shfl_xor; 3-shfl gate gather; one barrier (nw=8) per step.
// =====================================================================
__global__ __launch_bounds__(256)
void lstm_kernel(const float* __restrict__ w_hh)
{
    __shared__ float h_s[2][64];
    const int b = blockIdx.x;
    const int tid = threadIdx.x;
    const int warp = tid >> 5, lane = tid & 31;
    const int g = lane & 3;
    const int u = warp * 8 + (lane >> 2);
    const int base = lane & 28;      // first lane of this unit's 4-lane group

    const int grow = g * 64 + u;     // gate row, PyTorch order i,f,g,o
    unsigned long long w2[32];
#pragma unroll
    for (int k = 0; k < 32; ++k) {
        float lo = w_hh[grow * 64 + 2 * k];
        float hi = w_hh[grow * 64 + 2 * k + 1];
        asm("mov.b64 %0, {%1, %2};" : "=l"(w2[k]) : "f"(lo), "f"(hi));
    }
    float c = 0.f;
    if (tid < 64) h_s[0][tid] = 0.f;
    __syncthreads();

    const float* xgb = g_xg + (size_t)b * 128 * 256;
    float* lob = g_lstm + (size_t)b * 128 * 64;

    float xnext = xgb[grow];
    for (int t = 0; t < 128; ++t) {
        const unsigned long long* hp = (const unsigned long long*)h_s[t & 1];
        unsigned long long a0 = 0ull, a1 = 0ull, a2 = 0ull, a3 = 0ull;
#pragma unroll
        for (int k = 0; k < 8; ++k) {
            asm("fma.rn.f32x2 %0, %1, %2, %0;" : "+l"(a0) : "l"(w2[4 * k]),     "l"(hp[4 * k]));
            asm("fma.rn.f32x2 %0, %1, %2, %0;" : "+l"(a1) : "l"(w2[4 * k + 1]), "l"(hp[4 * k + 1]));
            asm("fma.rn.f32x2 %0, %1, %2, %0;" : "+l"(a2) : "l"(w2[4 * k + 2]), "l"(hp[4 * k + 2]));
            asm("fma.rn.f32x2 %0, %1, %2, %0;" : "+l"(a3) : "l"(w2[4 * k + 3]), "l"(hp[4 * k + 3]));
        }
        unsigned long long s01, s23, st;
        asm("add.rn.f32x2 %0, %1, %2;" : "=l"(s01) : "l"(a0), "l"(a1));
        asm("add.rn.f32x2 %0, %1, %2;" : "=l"(s23) : "l"(a2), "l"(a3));
        asm("add.rn.f32x2 %0, %1, %2;" : "=l"(st) : "l"(s01), "l"(s23));
        float slo, shi;
        asm("mov.b64 {%0, %1}, %2;" : "=f"(slo), "=f"(shi) : "l"(st));
        float s = slo + shi + xnext;
        if (t < 127) xnext = xgb[(t + 1) * 256 + grow];

        // in-lane activation (parallel across the 4 gate lanes)
        float act = (g == 2) ? fast_tanh(s) : fast_sigmoid(s);
        float ai = __shfl_sync(0xffffffffu, act, base + 0);
        float af = __shfl_sync(0xffffffffu, act, base + 1);
        float ag = __shfl_sync(0xffffffffu, act, base + 2);
        float ao = __shfl_sync(0xffffffffu, act, base + 3);
        if (g == 0) {
            c = af * c + ai * ag;
            float h = ao * fast_tanh(c);
            lob[t * 64 + u] = h;
            h_s[(t + 1) & 1][u] = h;
        }
        __syncthreads();
    }
}

// =====================================================================
// Kernel 5: fused policy/value heads — batched two-phase (unchanged)
// =====================================================================
__global__ __launch_bounds__(256)
void heads_kernel(const float* __restrict__ p1w, const float* __restrict__ p1b,
                  const float* __restrict__ p2w, const float* __restrict__ p2b,
                  const float* __restrict__ v1w, const float* __restrict__ v1b,
                  const float* __restrict__ v2w, const float* __restrict__ v2b,
                  float* __restrict__ out)
{
    __shared__ float h_s[32][64];
    __shared__ float u_s[32][260];
    __shared__ float p2s[6 * 128];
    __shared__ float v2s[128];

    const int f0 = blockIdx.x * 32;
    const int t = threadIdx.x;

    const float* wsrc = (t < 128) ? (p1w + t * 64) : (v1w + (t - 128) * 64);
    float w[64];
#pragma unroll
    for (int k = 0; k < 64; ++k) w[k] = wsrc[k];
    const float bias = (t < 128) ? p1b[t] : v1b[t - 128];

    for (int i = t; i < 32 * 64; i += 256) h_s[i / 64][i % 64] = g_lstm[(size_t)f0 * 64 + i];
    for (int i = t; i < 768; i += 256) p2s[i] = p2w[i];
    if (t < 128) v2s[t] = v2w[t];
    __syncthreads();

    for (int fi = 0; fi < 32; fi += 2) {
        float sA = bias, sB = bias;
#pragma unroll
        for (int k = 0; k < 64; ++k) {
            sA = fmaf(w[k], h_s[fi][k], sA);
            sB = fmaf(w[k], h_s[fi + 1][k], sB);
        }
        u_s[fi][t]     = fmaxf(sA, 0.f);
        u_s[fi + 1][t] = fmaxf(sB, 0.f);
    }
    __syncthreads();

    const int f = t >> 3, j = t & 7;
    if (j < 6) {
        const float* pw = p2s + j * 128;
        const float* us = u_s[f];
        float s0 = 0.f, s1 = 0.f;
#pragma unroll
        for (int k = 0; k < 128; k += 2) {
            s0 = fmaf(pw[k], us[k], s0);
            s1 = fmaf(pw[k + 1], us[k + 1], s1);
        }
        out[(f0 + f) * 6 + j] = s0 + s1 + p2b[j];
    } else if (j == 6) {
        const float* us = u_s[f] + 128;
        float s0 = 0.f, s1 = 0.f;
#pragma unroll
        for (int k = 0; k < 128; k += 2) {
            s0 = fmaf(v2s[k], us[k], s0);
            s1 = fmaf(v2s[k + 1], us[k + 1], s1);
        }
        out[FRAMES * 6 + f0 + f] = s0 + s1 + v2b[0];
    }
}

// =====================================================================
extern "C" void kernel_launch(void* const* d_in, const int* in_sizes, int n_in,
                              void* d_out, int out_size)
{
    const float* x    = (const float*)d_in[0];
    const float* c0w  = (const float*)d_in[1];
    const float* c0b  = (const float*)d_in[2];
    const float* cws  = (const float*)d_in[3];
    const float* cbs  = (const float*)d_in[4];
    const float* fcw  = (const float*)d_in[5];
    const float* fcb  = (const float*)d_in[6];
    const float* wih  = (const float*)d_in[7];
    const float* whh  = (const float*)d_in[8];
    const float* bih  = (const float*)d_in[9];
    const float* bhh  = (const float*)d_in[10];
    const float* p1w  = (const float*)d_in[11];
    const float* p1b  = (const float*)d_in[12];
    const float* p2w  = (const float*)d_in[13];
    const float* p2b  = (const float*)d_in[14];
    const float* v1w  = (const float*)d_in[15];
    const float* v1b  = (const float*)d_in[16];
    const float* v2w  = (const float*)d_in[17];
    const float* v2b  = (const float*)d_in[18];
    float* out = (float*)d_out;

    cudaFuncSetAttribute(conv_mma_kernel,
                         cudaFuncAttributeMaxDynamicSharedMemorySize, SM_TOTAL);

    prep_kernel<<<(NBF + NWF + NWIH + 255) / 256, 256>>>(c0w, cws, fcw, wih);
    conv_mma_kernel<<<FRAMES, 256, SM_TOTAL>>>(x, c0b, cbs);
    fc_mma_kernel<<<dim3(FRAMES / 32, FC_SPLITS), 256>>>();
    xgates_kernel<<<FRAMES / 32, 256>>>(fcb, bih, bhh);
    lstm_kernel<<<32, 256>>>(whh);
    heads_kernel<<<FRAMES / 32, 256>>>(p1w, p1b, p2w, p2b, v1w, v1b, v2w, v2b, out);
}